// round 2
// baseline (speedup 1.0000x reference)
#include <cuda_runtime.h>
#include <cuda_bf16.h>
#include <math.h>

#define B_  64
#define T_  512
#define E_  512
#define H_  256
#define NT_ 20
#define G4  1024   /* 4*H */

// ---------------- scratch (device globals; no runtime allocation) -------------
__device__ float g_xA[B_ * T_ * E_];            // 64 MB  ping
__device__ float g_xB[B_ * T_ * E_];            // 64 MB  pong
__device__ float g_xg[(size_t)B_ * T_ * 2 * G4];// 256 MB input projections (both dirs)
__device__ float g_h[2 * 2 * B_ * H_];          // [dir][parity][b][u]
__device__ float g_em[B_ * T_ * NT_];           // emissions
__device__ float g_llh[B_];
__device__ unsigned g_cnt[8];
__device__ unsigned g_phs[8];

// ---------------- embedding gather -------------------------------------------
__global__ void k_gather(const int* __restrict__ ids, const float* __restrict__ embed) {
    int bt = blockIdx.x;                 // 0..B*T-1
    int id = ids[bt];
    int e  = threadIdx.x * 4;            // 128 threads * 4 floats = 512
    float4 v = *(const float4*)(embed + (size_t)id * E_ + e);
    *(float4*)(g_xA + (size_t)bt * E_ + e) = v;
}

// ---------------- zero an x buffer -------------------------------------------
__global__ void k_zero(int out_is_A) {
    float* p = out_is_A ? g_xA : g_xB;
    int i = blockIdx.x * blockDim.x + threadIdx.x;
    ((float4*)p)[i] = make_float4(0.f, 0.f, 0.f, 0.f);
}

// ---------------- input-projection SGEMM:  xg = X @ Wl^T + bias ---------------
// X: [32768, 512] row-major.  Wl: [2048, 512] row-major (dir-major rows).
#define BM 128
#define BN 128
#define BK 16
__global__ void __launch_bounds__(256) k_gemm(const float* __restrict__ w_ih,
                                              const float* __restrict__ b_ih,
                                              const float* __restrict__ b_hh,
                                              int layer, int in_is_A) {
    const float* X  = in_is_A ? g_xA : g_xB;
    const float* W  = w_ih + (size_t)layer * 2 * G4 * E_;
    const float* bi = b_ih + layer * 2 * G4;
    const float* bh = b_hh + layer * 2 * G4;

    __shared__ float As[BK][BM + 4];
    __shared__ float Bs[BK][BN + 4];

    int n0 = blockIdx.x * BN;
    int m0 = blockIdx.y * BM;
    int tid = threadIdx.x;
    int tx = tid & 15, ty = tid >> 4;

    float acc[8][8];
#pragma unroll
    for (int i = 0; i < 8; i++)
#pragma unroll
        for (int j = 0; j < 8; j++) acc[i][j] = 0.f;

    for (int k0 = 0; k0 < E_; k0 += BK) {
#pragma unroll
        for (int t2 = 0; t2 < 2; ++t2) {
            int idx = tid + t2 * 256;          // 0..511
            int row = idx >> 2;
            int kq  = idx & 3;
            float4 va = *(const float4*)(X + (size_t)(m0 + row) * E_ + k0 + kq * 4);
            As[kq * 4 + 0][row] = va.x;
            As[kq * 4 + 1][row] = va.y;
            As[kq * 4 + 2][row] = va.z;
            As[kq * 4 + 3][row] = va.w;
            float4 vb = *(const float4*)(W + (size_t)(n0 + row) * E_ + k0 + kq * 4);
            Bs[kq * 4 + 0][row] = vb.x;
            Bs[kq * 4 + 1][row] = vb.y;
            Bs[kq * 4 + 2][row] = vb.z;
            Bs[kq * 4 + 3][row] = vb.w;
        }
        __syncthreads();
#pragma unroll
        for (int kk = 0; kk < BK; ++kk) {
            float a[8], b[8];
            *(float4*)&a[0] = *(const float4*)&As[kk][ty * 8];
            *(float4*)&a[4] = *(const float4*)&As[kk][ty * 8 + 4];
            *(float4*)&b[0] = *(const float4*)&Bs[kk][tx * 8];
            *(float4*)&b[4] = *(const float4*)&Bs[kk][tx * 8 + 4];
#pragma unroll
            for (int i = 0; i < 8; i++)
#pragma unroll
                for (int j = 0; j < 8; j++) acc[i][j] += a[i] * b[j];
        }
        __syncthreads();
    }
#pragma unroll
    for (int i = 0; i < 8; i++) {
        int m = m0 + ty * 8 + i;
#pragma unroll
        for (int j = 0; j < 8; j += 4) {
            int n = n0 + tx * 8 + j;
            float4 o;
            o.x = acc[i][j + 0] + bi[n + 0] + bh[n + 0];
            o.y = acc[i][j + 1] + bi[n + 1] + bh[n + 1];
            o.z = acc[i][j + 2] + bi[n + 2] + bh[n + 2];
            o.w = acc[i][j + 3] + bi[n + 3] + bh[n + 3];
            *(float4*)(g_xg + (size_t)m * 2048 + n) = o;
        }
    }
}

// ---------------- persistent BiLSTM layer kernel ------------------------------
// 128 CTAs: dir(2) x unit-block(16) x batch-block(4).  256 threads: u(16) x n(16).
// Sync group = 16 CTAs sharing (dir, batch-block); h exchanged through L2.
#define LSTM_SMEM ((256 * 64 + 16 * 256) * 4)

__global__ void __launch_bounds__(256, 1) k_lstm(const float* __restrict__ w_hh,
                                                 const int* __restrict__ lengths,
                                                 int layer, int out_is_A) {
    extern __shared__ float smem[];
    float* w_s  = smem;              // [k=256][u*4+g] : 64 KB
    float* h_sh = smem + 256 * 64;   // [16][256]      : 16 KB
    __shared__ int len_sh[16];
    __shared__ unsigned phase0_sh;

    float* xout = out_is_A ? g_xA : g_xB;
    int cta = blockIdx.x;
    int dir = cta >> 6;
    int lo  = cta & 63;
    int ub  = lo & 15;
    int bb  = lo >> 4;
    int grp = dir * 4 + bb;
    int tid = threadIdx.x;
    int u = tid & 15, n = tid >> 4;
    int b  = bb * 16 + n;
    int ug = ub * 16 + u;

    const float* whh = w_hh + ((size_t)layer * 2 + dir) * G4 * H_;  // [1024][256]
    // w_s[k*64 + up*4+g] = whh[(g*256 + ub*16 + up)*256 + k]
    for (int idx = tid; idx < 64 * 256; idx += 256) {
        int c = idx >> 8;            // column 0..63 (iteration)
        int k = idx & 255;           // = tid : coalesced global read
        int up = c >> 2, g = c & 3;
        w_s[k * 64 + c] = whh[(size_t)(g * 256 + ub * 16 + up) * 256 + k];
    }
    if (tid < 16) len_sh[tid] = lengths[bb * 16 + tid];
    if (tid == 0) phase0_sh = *(volatile unsigned*)&g_phs[grp];
    __syncthreads();
    int len = len_sh[n];
    int maxlen = 0;
#pragma unroll
    for (int i = 0; i < 16; i++) maxlen = max(maxlen, len_sh[i]);
    unsigned pbase = phase0_sh;

    float cst = 0.f;
    const float* xg_b = g_xg + (size_t)b * T_ * 2048 + dir * G4 + ug;

    for (int s = 0; s < maxlen; ++s) {
        int rb = s & 1;
        if (s == 0) {
            for (int i = tid; i < 1024; i += 256)
                *(float4*)&h_sh[i * 4] = make_float4(0.f, 0.f, 0.f, 0.f);
        } else {
            const float* hsrc = g_h + ((size_t)(dir * 2 + rb) * B_ + bb * 16) * H_;
            for (int i = tid; i < 1024; i += 256) {
                float4 v = __ldcg((const float4*)(hsrc + i * 4));  // L2-coherent
                *(float4*)&h_sh[i * 4] = v;
            }
        }
        __syncthreads();

        if (s < len) {
            int pos = dir ? (len - 1 - s) : s;
            const float* xgp = xg_b + (size_t)pos * 2048;
            float a0 = xgp[0], a1 = xgp[256], a2 = xgp[512], a3 = xgp[768];
            const float* hrow = h_sh + n * 256;
            const float* wcol = w_s + u * 4;
#pragma unroll 4
            for (int k = 0; k < 256; k += 4) {
                float4 hv = *(const float4*)(hrow + k);
                float4 w0 = *(const float4*)(wcol + (k + 0) * 64);
                float4 w1 = *(const float4*)(wcol + (k + 1) * 64);
                float4 w2 = *(const float4*)(wcol + (k + 2) * 64);
                float4 w3 = *(const float4*)(wcol + (k + 3) * 64);
                a0 += w0.x * hv.x + w1.x * hv.y + w2.x * hv.z + w3.x * hv.w;
                a1 += w0.y * hv.x + w1.y * hv.y + w2.y * hv.z + w3.y * hv.w;
                a2 += w0.z * hv.x + w1.z * hv.y + w2.z * hv.z + w3.z * hv.w;
                a3 += w0.w * hv.x + w1.w * hv.y + w2.w * hv.z + w3.w * hv.w;
            }
            float ig = 1.f / (1.f + expf(-a0));
            float fg = 1.f / (1.f + expf(-a1));
            float gg = tanhf(a2);
            float og = 1.f / (1.f + expf(-a3));
            cst = fg * cst + ig * gg;
            float hv = og * tanhf(cst);
            g_h[((size_t)(dir * 2 + (rb ^ 1)) * B_ + b) * H_ + ug] = hv;
            xout[((size_t)b * T_ + pos) * E_ + dir * H_ + ug] = hv;
        }
        __threadfence();
        __syncthreads();
        if (tid == 0) {
            unsigned target = pbase + (unsigned)s + 1u;
            if (atomicAdd(&g_cnt[grp], 1u) == 15u) {
                atomicExch(&g_cnt[grp], 0u);
                __threadfence();
                atomicAdd(&g_phs[grp], 1u);
            } else {
                while ((int)(*(volatile unsigned*)&g_phs[grp] - target) < 0) {}
                __threadfence();
            }
        }
        __syncthreads();
    }
}

// ---------------- emissions: x_final @ fc_w + fc_b ----------------------------
__global__ void k_emis(const float* __restrict__ fc_w, const float* __restrict__ fc_b) {
    int w    = blockIdx.x * 8 + (threadIdx.x >> 5);   // row 0..32767
    int lane = threadIdx.x & 31;
    int j    = lane < NT_ ? lane : 0;
    const float* x = g_xA + (size_t)w * E_;
    float acc = fc_b[j];
#pragma unroll 4
    for (int k = 0; k < E_; k += 4) {
        float4 xv = *(const float4*)(x + k);
        acc += xv.x * fc_w[(k + 0) * NT_ + j] + xv.y * fc_w[(k + 1) * NT_ + j]
             + xv.z * fc_w[(k + 2) * NT_ + j] + xv.w * fc_w[(k + 3) * NT_ + j];
    }
    if (lane < NT_) g_em[(size_t)w * NT_ + lane] = acc;
}

// ---------------- CRF: numerator + forward logsumexp scan ---------------------
__global__ void k_crf(const int* __restrict__ tags, const int* __restrict__ lengths,
                      const float* __restrict__ crf_start, const float* __restrict__ crf_end,
                      const float* __restrict__ crf_trans) {
    int b    = blockIdx.x;
    int lane = threadIdx.x;
    int len  = lengths[b];
    const int*   tg = tags + b * T_;
    const float* em = g_em + (size_t)b * T_ * NT_;

    // numerator
    float part = 0.f;
    for (int t = lane; t < T_; t += 32) {
        if (t < len) {
            int tt = tg[t];
            part += em[t * NT_ + tt];
            if (t >= 1) part += crf_trans[tg[t - 1] * NT_ + tt];
        }
    }
#pragma unroll
    for (int o = 16; o; o >>= 1) part += __shfl_xor_sync(0xFFFFFFFFu, part, o);
    float numer = part + crf_start[tg[0]] + crf_end[tg[len - 1]];

    int j = lane < NT_ ? lane : 0;
    float trT[NT_];
#pragma unroll
    for (int i = 0; i < NT_; i++) trT[i] = crf_trans[i * NT_ + j];

    float s = crf_start[j] + em[j];
    for (int t = 1; t < len; ++t) {
        float sv[NT_];
        float m = -1e30f;
#pragma unroll
        for (int i = 0; i < NT_; i++) {
            float si = __shfl_sync(0xFFFFFFFFu, s, i);
            sv[i] = si + trT[i];
            m = fmaxf(m, sv[i]);
        }
        float z = 0.f;
#pragma unroll
        for (int i = 0; i < NT_; i++) z += expf(sv[i] - m);
        s = m + logf(z) + em[t * NT_ + j];
    }
    s += crf_end[j];
    float sj = (lane < NT_) ? s : -1e30f;
    float mm = sj;
#pragma unroll
    for (int o = 16; o; o >>= 1) mm = fmaxf(mm, __shfl_xor_sync(0xFFFFFFFFu, mm, o));
    float zz = (lane < NT_) ? expf(sj - mm) : 0.f;
#pragma unroll
    for (int o = 16; o; o >>= 1) zz += __shfl_xor_sync(0xFFFFFFFFu, zz, o);
    float logZ = mm + logf(zz);
    if (lane == 0) g_llh[b] = numer - logZ;
}

// ---------------- final reduction ---------------------------------------------
__global__ void k_reduce(float* __restrict__ out) {
    int lane = threadIdx.x;          // 64 threads
    float v = g_llh[lane];
    __shared__ float tmp[2];
#pragma unroll
    for (int o = 16; o; o >>= 1) v += __shfl_xor_sync(0xFFFFFFFFu, v, o);
    if ((lane & 31) == 0) tmp[lane >> 5] = v;
    __syncthreads();
    if (lane == 0) out[0] = -(tmp[0] + tmp[1]);
}

// ---------------- host launcher ------------------------------------------------
extern "C" void kernel_launch(void* const* d_in, const int* in_sizes, int n_in,
                              void* d_out, int out_size) {
    const int*   ids   = (const int*)d_in[0];
    const int*   lens  = (const int*)d_in[1];
    const int*   tags  = (const int*)d_in[2];
    const float* embed = (const float*)d_in[3];
    const float* w_ih  = (const float*)d_in[4];
    const float* w_hh  = (const float*)d_in[5];
    const float* b_ih  = (const float*)d_in[6];
    const float* b_hh  = (const float*)d_in[7];
    const float* fc_w  = (const float*)d_in[8];
    const float* fc_b  = (const float*)d_in[9];
    const float* c_st  = (const float*)d_in[10];
    const float* c_en  = (const float*)d_in[11];
    const float* c_tr  = (const float*)d_in[12];
    float* out = (float*)d_out;

    cudaFuncSetAttribute(k_lstm, cudaFuncAttributeMaxDynamicSharedMemorySize, LSTM_SMEM);

    k_gather<<<B_ * T_, 128>>>(ids, embed);
    for (int layer = 0; layer < 2; ++layer) {
        int in_is_A = (layer == 0) ? 1 : 0;
        k_gemm<<<dim3(2048 / BN, 32768 / BM), 256>>>(w_ih, b_ih, b_hh, layer, in_is_A);
        k_zero<<<(B_ * T_ * E_ / 4) / 256, 256>>>(!in_is_A);
        k_lstm<<<128, 256, LSTM_SMEM>>>(w_hh, lens, layer, !in_is_A);
    }
    k_emis<<<B_ * T_ / 8, 256>>>(fc_w, fc_b);
    k_crf<<<B_, 32>>>(tags, lens, c_st, c_en, c_tr);
    k_reduce<<<1, 64>>>(out);
}

// round 4
// speedup vs baseline: 2.5531x; 2.5531x over previous
#include <cuda_runtime.h>
#include <cuda_bf16.h>
#include <stdint.h>
#include <math.h>

#define B_  64
#define T_  512
#define E_  512
#define H_  256
#define NT_ 20

// ---------------- scratch (device globals) ------------------------------------
__device__ __nv_bfloat16 g_xbfA[B_ * T_ * E_];        // 32 MB  layer-0 input (bf16)
__device__ __nv_bfloat16 g_xbfB[B_ * T_ * E_];        // 32 MB  layer-1 input (bf16)
__device__ float g_xA[B_ * T_ * E_];                  // 64 MB  final layer output (fp32)
__device__ float g_xg[(size_t)B_ * T_ * 2048];        // 256 MB input projections
__device__ __nv_bfloat16 g_wbf[2 * 2048 * E_];        // 4 MB   w_ih in bf16
__device__ __nv_bfloat16 g_hbf[2 * 2 * B_ * H_];      // h exchange [dir][parity][b][u]
__device__ float g_em[B_ * T_ * NT_];
__device__ float g_llh[B_];
__device__ unsigned g_cnt[8];
__device__ unsigned g_phs[8];

// ---------------- small helpers ------------------------------------------------
__device__ __forceinline__ unsigned pack_bf2(float a, float b) {
    __nv_bfloat162 h2 = __floats2bfloat162_rn(a, b);
    return *reinterpret_cast<unsigned*>(&h2);
}
__device__ __forceinline__ void ldsm4(unsigned& a0, unsigned& a1, unsigned& a2, unsigned& a3,
                                      unsigned addr) {
    asm volatile("ldmatrix.sync.aligned.m8n8.x4.shared.b16 {%0,%1,%2,%3}, [%4];\n"
                 : "=r"(a0), "=r"(a1), "=r"(a2), "=r"(a3) : "r"(addr));
}
__device__ __forceinline__ void mma_bf(float& d0, float& d1, float& d2, float& d3,
                                       unsigned a0, unsigned a1, unsigned a2, unsigned a3,
                                       unsigned b0, unsigned b1) {
    asm volatile("mma.sync.aligned.m16n8k16.row.col.f32.bf16.bf16.f32 "
                 "{%0,%1,%2,%3},{%4,%5,%6,%7},{%8,%9},{%0,%1,%2,%3};\n"
                 : "+f"(d0), "+f"(d1), "+f"(d2), "+f"(d3)
                 : "r"(a0), "r"(a1), "r"(a2), "r"(a3), "r"(b0), "r"(b1));
}
__device__ __forceinline__ float sigm(float x) { return 1.f / (1.f + __expf(-x)); }
__device__ __forceinline__ float tanh_(float x) {
    float ax = fabsf(x);
    float e = __expf(-2.f * ax);
    float t = (1.f - e) / (1.f + e);
    return copysignf(t, x);
}

// ---------------- conversion / gather / zero ----------------------------------
__global__ void k_wcvt(const float* __restrict__ w_ih) {
    int i = (blockIdx.x * 256 + threadIdx.x) * 4;
    float4 v = *(const float4*)(w_ih + i);
    uint2 o;
    o.x = pack_bf2(v.x, v.y);
    o.y = pack_bf2(v.z, v.w);
    *(uint2*)(g_wbf + i) = o;
}

__global__ void k_gather(const int* __restrict__ ids, const float* __restrict__ embed) {
    int bt = blockIdx.x;
    int id = ids[bt];
    int e = threadIdx.x * 4;
    float4 v = *(const float4*)(embed + (size_t)id * E_ + e);
    uint2 o;
    o.x = pack_bf2(v.x, v.y);
    o.y = pack_bf2(v.z, v.w);
    *(uint2*)(g_xbfA + (size_t)bt * E_ + e) = o;
}

__global__ void k_zerobf() {   // zero g_xbfB
    int i = blockIdx.x * 256 + threadIdx.x;
    ((uint4*)g_xbfB)[i] = make_uint4(0, 0, 0, 0);
}
__global__ void k_zerof() {    // zero g_xA
    int i = blockIdx.x * 256 + threadIdx.x;
    ((uint4*)g_xA)[i] = make_uint4(0, 0, 0, 0);
}

// ---------------- bf16 tensor-core GEMM: xg = X @ W^T + bias -------------------
// X: [32768,512] bf16.  W: [2048,512] bf16 (row-major, n-major rows).
// CTA tile 128x128, K-chunk 32, 8 warps each 64x32.
__global__ void __launch_bounds__(256) k_gemm_bf(const float* __restrict__ b_ih,
                                                 const float* __restrict__ b_hh,
                                                 int layer) {
    __shared__ __align__(16) __nv_bfloat16 As[128 * 40];  // padded stride 40 (80B)
    __shared__ __align__(16) __nv_bfloat16 Bs[128 * 40];

    const __nv_bfloat16* Xbf = layer ? g_xbfB : g_xbfA;
    const __nv_bfloat16* Wbf = g_wbf + (size_t)layer * 2048 * E_;
    const float* bi = b_ih + layer * 2048;
    const float* bh = b_hh + layer * 2048;

    int m0 = blockIdx.y * 128, n0 = blockIdx.x * 128;
    int tid = threadIdx.x, w = tid >> 5, lane = tid & 31;

    const __nv_bfloat16* Ag = Xbf + (size_t)(m0 + (tid >> 2)) * E_ + (tid & 3) * 8;
    const __nv_bfloat16* Bg = Wbf + (size_t)(n0 + (tid >> 2)) * E_ + (tid & 3) * 8;
    int soff = (tid >> 2) * 40 + (tid & 3) * 8;

    unsigned a_base = (unsigned)__cvta_generic_to_shared(As);
    unsigned b_base = (unsigned)__cvta_generic_to_shared(Bs);

    int mbase = (w & 1) * 64, nbase = (w >> 1) * 32;

    float acc[4][4][4];
#pragma unroll
    for (int i = 0; i < 4; i++)
#pragma unroll
        for (int j = 0; j < 4; j++)
#pragma unroll
            for (int r = 0; r < 4; r++) acc[i][j][r] = 0.f;

    uint4 ra[2], rb[2];
#pragma unroll
    for (int i = 0; i < 2; i++) {
        ra[i] = *(const uint4*)(Ag + i * 64 * E_);
        rb[i] = *(const uint4*)(Bg + i * 64 * E_);
    }

    for (int kb = 0; kb < 16; ++kb) {
#pragma unroll
        for (int i = 0; i < 2; i++) {
            *(uint4*)&As[soff + i * 64 * 40] = ra[i];
            *(uint4*)&Bs[soff + i * 64 * 40] = rb[i];
        }
        __syncthreads();
        if (kb < 15) {
#pragma unroll
            for (int i = 0; i < 2; i++) {
                ra[i] = *(const uint4*)(Ag + (kb + 1) * 32 + i * 64 * E_);
                rb[i] = *(const uint4*)(Bg + (kb + 1) * 32 + i * 64 * E_);
            }
        }
#pragma unroll
        for (int kk = 0; kk < 32; kk += 16) {
            unsigned aF[4][4], bF[4][2];
#pragma unroll
            for (int mt = 0; mt < 4; ++mt) {
                int row = mbase + mt * 16 + (lane & 15);
                int col = kk + ((lane >> 4) << 3);
                ldsm4(aF[mt][0], aF[mt][1], aF[mt][2], aF[mt][3],
                      a_base + (unsigned)(row * 40 + col) * 2);
            }
#pragma unroll
            for (int p = 0; p < 2; ++p) {
                int row = nbase + 16 * p + ((lane >> 4) << 3) + (lane & 7);
                int colb = kk + (((lane >> 3) & 1) << 3);
                ldsm4(bF[2 * p][0], bF[2 * p][1], bF[2 * p + 1][0], bF[2 * p + 1][1],
                      b_base + (unsigned)(row * 40 + colb) * 2);
            }
#pragma unroll
            for (int mt = 0; mt < 4; ++mt)
#pragma unroll
                for (int nt = 0; nt < 4; ++nt)
                    mma_bf(acc[mt][nt][0], acc[mt][nt][1], acc[mt][nt][2], acc[mt][nt][3],
                           aF[mt][0], aF[mt][1], aF[mt][2], aF[mt][3],
                           bF[nt][0], bF[nt][1]);
        }
        __syncthreads();
    }

    // epilogue: add bias, write fp32
#pragma unroll
    for (int nt = 0; nt < 4; ++nt) {
        int coln = n0 + nbase + 8 * nt + 2 * (lane & 3);
        float bb0 = bi[coln] + bh[coln];
        float bb1 = bi[coln + 1] + bh[coln + 1];
#pragma unroll
        for (int mt = 0; mt < 4; ++mt) {
            int row = m0 + mbase + 16 * mt + (lane >> 2);
            *(float2*)&g_xg[(size_t)row * 2048 + coln] =
                make_float2(acc[mt][nt][0] + bb0, acc[mt][nt][1] + bb1);
            *(float2*)&g_xg[(size_t)(row + 8) * 2048 + coln] =
                make_float2(acc[mt][nt][2] + bb0, acc[mt][nt][3] + bb1);
        }
    }
}

// ---------------- persistent BiLSTM layer: weight-stationary mma ---------------
// 128 CTAs: dir(2) x unit-block(16) x batch-block(4).  8 warps, each owns 8 cols.
__global__ void __launch_bounds__(256, 1) k_lstm(const float* __restrict__ w_hh,
                                                 const int* __restrict__ lengths,
                                                 int layer, int out_fp32) {
    __shared__ __align__(16) __nv_bfloat16 h_sh[16 * 264];  // stride 264 bf16 (528B)
    __shared__ __align__(16) float pre_sh[16 * 66];         // stride 66 floats
    __shared__ int len_sh[16];
    __shared__ unsigned phase0_sh;

    int cta = blockIdx.x;
    int dir = cta >> 6;
    int lo = cta & 63;
    int ub = lo & 15;
    int bb = lo >> 4;
    int grp = dir * 4 + bb;
    int tid = threadIdx.x;
    int w = tid >> 5, lane = tid & 31;

    // ---- B fragments (weights) resident in registers ----
    int c = 8 * w + (lane >> 2);                       // CTA col 0..63
    int gr = (c >> 4) * 256 + ub * 16 + (c & 15);      // row within dir's 4H
    const float* wr = w_hh + ((size_t)(layer * 2 + dir) * 1024 + gr) * 256;
    int q2 = (lane & 3) * 2;
    unsigned bfr[16][2];
#pragma unroll
    for (int kt = 0; kt < 16; ++kt) {
        bfr[kt][0] = pack_bf2(wr[kt * 16 + q2],     wr[kt * 16 + q2 + 1]);
        bfr[kt][1] = pack_bf2(wr[kt * 16 + q2 + 8], wr[kt * 16 + q2 + 9]);
    }

    if (tid < 16) len_sh[tid] = lengths[bb * 16 + tid];
    if (tid == 0) phase0_sh = *(volatile unsigned*)&g_phs[grp];
    __syncthreads();
    int blocal = tid >> 4, ulocal = tid & 15;
    int len_b = len_sh[blocal];
    int maxlen = 0;
#pragma unroll
    for (int i = 0; i < 16; i++) maxlen = max(maxlen, len_sh[i]);
    unsigned pbase = phase0_sh;

    int b = bb * 16 + blocal;
    int gu = ub * 16 + ulocal;
    const float* xg_t = g_xg + (size_t)b * T_ * 2048 + dir * 1024 + gu;

    unsigned h_base = (unsigned)__cvta_generic_to_shared(h_sh);
    unsigned a_addr = h_base + (unsigned)(lane & 15) * 528 + ((lane >> 4) << 4);

    float cst = 0.f;

    for (int s = 0; s < maxlen; ++s) {
        int rb = s & 1;
        // prefetch xg for this thread (b, 4 gates)
        float xg0 = 0.f, xg1 = 0.f, xg2 = 0.f, xg3 = 0.f;
        int pos = dir ? (len_b - 1 - s) : s;
        if (s < len_b) {
            const float* p = xg_t + (size_t)pos * 2048;
            xg0 = p[0]; xg1 = p[256]; xg2 = p[512]; xg3 = p[768];
        }
        // fill h_sh (16 batches x 256 units, bf16)
        {
            int row = tid >> 4, col16 = (tid & 15) * 16;
            uint4* dst = (uint4*)&h_sh[row * 264 + col16];
            if (s == 0) {
                dst[0] = make_uint4(0, 0, 0, 0);
                dst[1] = make_uint4(0, 0, 0, 0);
            } else {
                const uint4* src = (const uint4*)(g_hbf +
                    ((size_t)(dir * 2 + rb) * B_ + bb * 16 + row) * H_ + col16);
                dst[0] = __ldcg(src);
                dst[1] = __ldcg(src + 1);
            }
        }
        __syncthreads();

        // mma: pre[16 batch][8 cols of this warp] = h @ W^T
        float c0 = 0.f, c1 = 0.f, c2 = 0.f, c3 = 0.f;
#pragma unroll
        for (int kt = 0; kt < 16; ++kt) {
            unsigned a0, a1, a2, a3;
            ldsm4(a0, a1, a2, a3, a_addr + kt * 32);
            mma_bf(c0, c1, c2, c3, a0, a1, a2, a3, bfr[kt][0], bfr[kt][1]);
        }
        {
            int r = lane >> 2, cc = 8 * w + 2 * (lane & 3);
            *(float2*)&pre_sh[r * 66 + cc] = make_float2(c0, c1);
            *(float2*)&pre_sh[(r + 8) * 66 + cc] = make_float2(c2, c3);
        }
        __syncthreads();

        if (s < len_b) {
            const float* pr = pre_sh + blocal * 66 + ulocal;
            float a0 = xg0 + pr[0];
            float a1 = xg1 + pr[16];
            float a2 = xg2 + pr[32];
            float a3 = xg3 + pr[48];
            float ig = sigm(a0), fg = sigm(a1), gg = tanh_(a2), og = sigm(a3);
            cst = fg * cst + ig * gg;
            float hv = og * tanh_(cst);
            g_hbf[((size_t)(dir * 2 + (rb ^ 1)) * B_ + b) * H_ + gu] = __float2bfloat16(hv);
            size_t xoff = ((size_t)b * T_ + pos) * E_ + dir * H_ + gu;
            if (out_fp32) g_xA[xoff] = hv;
            else          g_xbfB[xoff] = __float2bfloat16(hv);
        }
        __threadfence();
        __syncthreads();
        if (tid == 0) {
            unsigned target = pbase + (unsigned)s + 1u;
            if (atomicAdd(&g_cnt[grp], 1u) == 15u) {
                atomicExch(&g_cnt[grp], 0u);
                __threadfence();
                atomicAdd(&g_phs[grp], 1u);
            } else {
                while ((int)(*(volatile unsigned*)&g_phs[grp] - target) < 0) {}
                __threadfence();
            }
        }
        __syncthreads();
    }
}

// ---------------- emissions -----------------------------------------------------
__global__ void k_emis(const float* __restrict__ fc_w, const float* __restrict__ fc_b) {
    int w = blockIdx.x * 8 + (threadIdx.x >> 5);
    int lane = threadIdx.x & 31;
    int j = lane < NT_ ? lane : 0;
    const float* x = g_xA + (size_t)w * E_;
    float acc = fc_b[j];
#pragma unroll 4
    for (int k = 0; k < E_; k += 4) {
        float4 xv = *(const float4*)(x + k);
        acc += xv.x * fc_w[(k + 0) * NT_ + j] + xv.y * fc_w[(k + 1) * NT_ + j]
             + xv.z * fc_w[(k + 2) * NT_ + j] + xv.w * fc_w[(k + 3) * NT_ + j];
    }
    if (lane < NT_) g_em[(size_t)w * NT_ + lane] = acc;
}

// ---------------- CRF -----------------------------------------------------------
__global__ void k_crf(const int* __restrict__ tags, const int* __restrict__ lengths,
                      const float* __restrict__ crf_start, const float* __restrict__ crf_end,
                      const float* __restrict__ crf_trans) {
    int b = blockIdx.x;
    int lane = threadIdx.x;
    int len = lengths[b];
    const int* tg = tags + b * T_;
    const float* em = g_em + (size_t)b * T_ * NT_;

    float part = 0.f;
    for (int t = lane; t < T_; t += 32) {
        if (t < len) {
            int tt = tg[t];
            part += em[t * NT_ + tt];
            if (t >= 1) part += crf_trans[tg[t - 1] * NT_ + tt];
        }
    }
#pragma unroll
    for (int o = 16; o; o >>= 1) part += __shfl_xor_sync(0xFFFFFFFFu, part, o);
    float numer = part + crf_start[tg[0]] + crf_end[tg[len - 1]];

    int j = lane < NT_ ? lane : 0;
    float trT[NT_];
#pragma unroll
    for (int i = 0; i < NT_; i++) trT[i] = crf_trans[i * NT_ + j];

    float s = crf_start[j] + em[j];
    for (int t = 1; t < len; ++t) {
        float sv[NT_];
        float m = -1e30f;
#pragma unroll
        for (int i = 0; i < NT_; i++) {
            float si = __shfl_sync(0xFFFFFFFFu, s, i);
            sv[i] = si + trT[i];
            m = fmaxf(m, sv[i]);
        }
        float z = 0.f;
#pragma unroll
        for (int i = 0; i < NT_; i++) z += expf(sv[i] - m);
        s = m + logf(z) + em[t * NT_ + j];
    }
    s += crf_end[j];
    float sj = (lane < NT_) ? s : -1e30f;
    float mm = sj;
#pragma unroll
    for (int o = 16; o; o >>= 1) mm = fmaxf(mm, __shfl_xor_sync(0xFFFFFFFFu, mm, o));
    float zz = (lane < NT_) ? expf(sj - mm) : 0.f;
#pragma unroll
    for (int o = 16; o; o >>= 1) zz += __shfl_xor_sync(0xFFFFFFFFu, zz, o);
    float logZ = mm + logf(zz);
    if (lane == 0) g_llh[b] = numer - logZ;
}

// ---------------- final reduction ----------------------------------------------
__global__ void k_reduce(float* __restrict__ out) {
    int lane = threadIdx.x;
    float v = g_llh[lane];
    __shared__ float tmp[2];
#pragma unroll
    for (int o = 16; o; o >>= 1) v += __shfl_xor_sync(0xFFFFFFFFu, v, o);
    if ((lane & 31) == 0) tmp[lane >> 5] = v;
    __syncthreads();
    if (lane == 0) out[0] = -(tmp[0] + tmp[1]);
}

// ---------------- host launcher -------------------------------------------------
extern "C" void kernel_launch(void* const* d_in, const int* in_sizes, int n_in,
                              void* d_out, int out_size) {
    const int*   ids   = (const int*)d_in[0];
    const int*   lens  = (const int*)d_in[1];
    const int*   tags  = (const int*)d_in[2];
    const float* embed = (const float*)d_in[3];
    const float* w_ih  = (const float*)d_in[4];
    const float* w_hh  = (const float*)d_in[5];
    const float* b_ih  = (const float*)d_in[6];
    const float* b_hh  = (const float*)d_in[7];
    const float* fc_w  = (const float*)d_in[8];
    const float* fc_b  = (const float*)d_in[9];
    const float* c_st  = (const float*)d_in[10];
    const float* c_en  = (const float*)d_in[11];
    const float* c_tr  = (const float*)d_in[12];
    float* out = (float*)d_out;

    k_wcvt<<<2048, 256>>>(w_ih);
    k_gather<<<B_ * T_, 128>>>(ids, embed);

    // layer 0
    k_gemm_bf<<<dim3(16, 256), 256>>>(b_ih, b_hh, 0);
    k_zerobf<<<8192, 256>>>();
    k_lstm<<<128, 256>>>(w_hh, lens, 0, 0);

    // layer 1
    k_gemm_bf<<<dim3(16, 256), 256>>>(b_ih, b_hh, 1);
    k_zerof<<<16384, 256>>>();
    k_lstm<<<128, 256>>>(w_hh, lens, 1, 1);

    k_emis<<<B_ * T_ / 8, 256>>>(fc_w, fc_b);
    k_crf<<<B_, 32>>>(tags, lens, c_st, c_en, c_tr);
    k_reduce<<<1, 64>>>(out);
}

// round 5
// speedup vs baseline: 3.0634x; 1.1999x over previous
#include <cuda_runtime.h>
#include <cuda_bf16.h>
#include <stdint.h>
#include <math.h>

#define B_  64
#define T_  512
#define E_  512
#define H_  256
#define NT_ 20

// ---------------- scratch (device globals) ------------------------------------
__device__ __nv_bfloat16 g_xbfA[B_ * T_ * E_];        // 32 MB  layer-0 input (bf16)
__device__ __nv_bfloat16 g_xbfB[B_ * T_ * E_];        // 32 MB  layer-1 input (bf16)
__device__ float g_xA[B_ * T_ * E_];                  // 64 MB  final layer output (fp32)
__device__ float g_xg[(size_t)B_ * T_ * 2048];        // 256 MB input projections
__device__ __nv_bfloat16 g_wbf[2 * 2048 * E_];        // 4 MB   w_ih in bf16
__device__ float g_em[B_ * T_ * NT_];
__device__ float g_llh[B_];

// ---------------- small helpers ------------------------------------------------
__device__ __forceinline__ unsigned pack_bf2(float a, float b) {
    __nv_bfloat162 h2 = __floats2bfloat162_rn(a, b);
    return *reinterpret_cast<unsigned*>(&h2);
}
__device__ __forceinline__ void ldsm4(unsigned& a0, unsigned& a1, unsigned& a2, unsigned& a3,
                                      unsigned addr) {
    asm volatile("ldmatrix.sync.aligned.m8n8.x4.shared.b16 {%0,%1,%2,%3}, [%4];\n"
                 : "=r"(a0), "=r"(a1), "=r"(a2), "=r"(a3) : "r"(addr));
}
__device__ __forceinline__ void mma_bf(float& d0, float& d1, float& d2, float& d3,
                                       unsigned a0, unsigned a1, unsigned a2, unsigned a3,
                                       unsigned b0, unsigned b1) {
    asm volatile("mma.sync.aligned.m16n8k16.row.col.f32.bf16.bf16.f32 "
                 "{%0,%1,%2,%3},{%4,%5,%6,%7},{%8,%9},{%0,%1,%2,%3};\n"
                 : "+f"(d0), "+f"(d1), "+f"(d2), "+f"(d3)
                 : "r"(a0), "r"(a1), "r"(a2), "r"(a3), "r"(b0), "r"(b1));
}
__device__ __forceinline__ unsigned mapa_u32(unsigned addr, int rank) {
    unsigned out;
    asm("mapa.shared::cluster.u32 %0, %1, %2;" : "=r"(out) : "r"(addr), "r"(rank));
    return out;
}
__device__ __forceinline__ unsigned long long ld_dsm64(unsigned addr) {
    unsigned long long v;
    asm volatile("ld.shared::cluster.b64 %0, [%1];" : "=l"(v) : "r"(addr));
    return v;
}
__device__ __forceinline__ float sigm(float x) { return 1.f / (1.f + __expf(-x)); }
__device__ __forceinline__ float tanh_(float x) {
    float ax = fabsf(x);
    float e = __expf(-2.f * ax);
    float t = (1.f - e) / (1.f + e);
    return copysignf(t, x);
}

// ---------------- conversion / gather / zero ----------------------------------
__global__ void k_wcvt(const float* __restrict__ w_ih) {
    int i = (blockIdx.x * 256 + threadIdx.x) * 4;
    float4 v = *(const float4*)(w_ih + i);
    uint2 o;
    o.x = pack_bf2(v.x, v.y);
    o.y = pack_bf2(v.z, v.w);
    *(uint2*)(g_wbf + i) = o;
}

__global__ void k_gather(const int* __restrict__ ids, const float* __restrict__ embed) {
    int bt = blockIdx.x;
    int id = ids[bt];
    int e = threadIdx.x * 4;
    float4 v = *(const float4*)(embed + (size_t)id * E_ + e);
    uint2 o;
    o.x = pack_bf2(v.x, v.y);
    o.y = pack_bf2(v.z, v.w);
    *(uint2*)(g_xbfA + (size_t)bt * E_ + e) = o;
}

__global__ void k_zerobf() {   // zero g_xbfB
    int i = blockIdx.x * 256 + threadIdx.x;
    ((uint4*)g_xbfB)[i] = make_uint4(0, 0, 0, 0);
}
__global__ void k_zerof() {    // zero g_xA
    int i = blockIdx.x * 256 + threadIdx.x;
    ((uint4*)g_xA)[i] = make_uint4(0, 0, 0, 0);
}

// ---------------- bf16 tensor-core GEMM: xg = X @ W^T + bias -------------------
__global__ void __launch_bounds__(256) k_gemm_bf(const float* __restrict__ b_ih,
                                                 const float* __restrict__ b_hh,
                                                 int layer) {
    __shared__ __align__(16) __nv_bfloat16 As[128 * 40];
    __shared__ __align__(16) __nv_bfloat16 Bs[128 * 40];

    const __nv_bfloat16* Xbf = layer ? g_xbfB : g_xbfA;
    const __nv_bfloat16* Wbf = g_wbf + (size_t)layer * 2048 * E_;
    const float* bi = b_ih + layer * 2048;
    const float* bh = b_hh + layer * 2048;

    int m0 = blockIdx.y * 128, n0 = blockIdx.x * 128;
    int tid = threadIdx.x, w = tid >> 5, lane = tid & 31;

    const __nv_bfloat16* Ag = Xbf + (size_t)(m0 + (tid >> 2)) * E_ + (tid & 3) * 8;
    const __nv_bfloat16* Bg = Wbf + (size_t)(n0 + (tid >> 2)) * E_ + (tid & 3) * 8;
    int soff = (tid >> 2) * 40 + (tid & 3) * 8;

    unsigned a_base = (unsigned)__cvta_generic_to_shared(As);
    unsigned b_base = (unsigned)__cvta_generic_to_shared(Bs);

    int mbase = (w & 1) * 64, nbase = (w >> 1) * 32;

    float acc[4][4][4];
#pragma unroll
    for (int i = 0; i < 4; i++)
#pragma unroll
        for (int j = 0; j < 4; j++)
#pragma unroll
            for (int r = 0; r < 4; r++) acc[i][j][r] = 0.f;

    uint4 ra[2], rb[2];
#pragma unroll
    for (int i = 0; i < 2; i++) {
        ra[i] = *(const uint4*)(Ag + i * 64 * E_);
        rb[i] = *(const uint4*)(Bg + i * 64 * E_);
    }

    for (int kb = 0; kb < 16; ++kb) {
#pragma unroll
        for (int i = 0; i < 2; i++) {
            *(uint4*)&As[soff + i * 64 * 40] = ra[i];
            *(uint4*)&Bs[soff + i * 64 * 40] = rb[i];
        }
        __syncthreads();
        if (kb < 15) {
#pragma unroll
            for (int i = 0; i < 2; i++) {
                ra[i] = *(const uint4*)(Ag + (kb + 1) * 32 + i * 64 * E_);
                rb[i] = *(const uint4*)(Bg + (kb + 1) * 32 + i * 64 * E_);
            }
        }
#pragma unroll
        for (int kk = 0; kk < 32; kk += 16) {
            unsigned aF[4][4], bF[4][2];
#pragma unroll
            for (int mt = 0; mt < 4; ++mt) {
                int row = mbase + mt * 16 + (lane & 15);
                int col = kk + ((lane >> 4) << 3);
                ldsm4(aF[mt][0], aF[mt][1], aF[mt][2], aF[mt][3],
                      a_base + (unsigned)(row * 40 + col) * 2);
            }
#pragma unroll
            for (int p = 0; p < 2; ++p) {
                int row = nbase + 16 * p + ((lane >> 4) << 3) + (lane & 7);
                int colb = kk + (((lane >> 3) & 1) << 3);
                ldsm4(bF[2 * p][0], bF[2 * p][1], bF[2 * p + 1][0], bF[2 * p + 1][1],
                      b_base + (unsigned)(row * 40 + colb) * 2);
            }
#pragma unroll
            for (int mt = 0; mt < 4; ++mt)
#pragma unroll
                for (int nt = 0; nt < 4; ++nt)
                    mma_bf(acc[mt][nt][0], acc[mt][nt][1], acc[mt][nt][2], acc[mt][nt][3],
                           aF[mt][0], aF[mt][1], aF[mt][2], aF[mt][3],
                           bF[nt][0], bF[nt][1]);
        }
        __syncthreads();
    }

#pragma unroll
    for (int nt = 0; nt < 4; ++nt) {
        int coln = n0 + nbase + 8 * nt + 2 * (lane & 3);
        float bb0 = bi[coln] + bh[coln];
        float bb1 = bi[coln + 1] + bh[coln + 1];
#pragma unroll
        for (int mt = 0; mt < 4; ++mt) {
            int row = m0 + mbase + 16 * mt + (lane >> 2);
            *(float2*)&g_xg[(size_t)row * 2048 + coln] =
                make_float2(acc[mt][nt][0] + bb0, acc[mt][nt][1] + bb1);
            *(float2*)&g_xg[(size_t)(row + 8) * 2048 + coln] =
                make_float2(acc[mt][nt][2] + bb0, acc[mt][nt][3] + bb1);
        }
    }
}

// ---------------- persistent BiLSTM layer: cluster + DSMEM h-exchange ----------
// 64 CTAs = 8 clusters of 8.  Cluster = (dir, batch-block of 16).
// CTA rank ub owns units [ub*32, ub*32+32) => 128 gate columns, 16 batches.
// 8 warps x 2 n-tiles (m16n8k16); B-frags (weights) in registers.
__global__ void __launch_bounds__(256, 1) __cluster_dims__(8, 1, 1)
k_lstm(const float* __restrict__ w_hh, const int* __restrict__ lengths,
       int layer, int out_fp32) {
    __shared__ __align__(16) __nv_bfloat16 h_sh[16 * 264];   // full h, stride 528 B
    __shared__ __align__(16) __nv_bfloat16 h_own[2][16 * 32];// own slice, dbl-buffered
    __shared__ __align__(16) float pre_sh[16 * 132];         // recurrent preacts
    __shared__ int len_sh[16];

    int cta = blockIdx.x;
    int ub  = cta & 7;          // cluster rank
    int grp = cta >> 3;
    int bb  = grp & 3;
    int dir = grp >> 2;
    int tid = threadIdx.x;
    int w = tid >> 5, lane = tid & 31;

    // ---- load B fragments (w_hh slice) into registers ----
    unsigned bfr[16][2][2];
    int q2 = (lane & 3) * 2;
#pragma unroll
    for (int p = 0; p < 2; ++p) {
        int col = 16 * w + 8 * p + (lane >> 2);           // CTA col 0..127
        int g = col >> 5, u = col & 31;
        const float* wr = w_hh +
            ((size_t)((layer * 2 + dir) * 1024 + g * 256 + ub * 32 + u)) * 256;
#pragma unroll
        for (int kt = 0; kt < 16; ++kt) {
            bfr[kt][p][0] = pack_bf2(wr[kt * 16 + q2],     wr[kt * 16 + q2 + 1]);
            bfr[kt][p][1] = pack_bf2(wr[kt * 16 + q2 + 8], wr[kt * 16 + q2 + 9]);
        }
    }
    if (tid < 16) len_sh[tid] = lengths[bb * 16 + tid];
    __syncthreads();
    int maxlen = 0;
#pragma unroll
    for (int i = 0; i < 16; i++) maxlen = max(maxlen, len_sh[i]);

    // gate-phase thread mapping: 2 batches x 1 unit per thread
    int u2 = tid & 31;
    int bq = tid >> 5;                 // 0..7
    int lb0 = bq, lb1 = bq + 8;
    int len0 = len_sh[lb0], len1 = len_sh[lb1];
    int gb0 = bb * 16 + lb0, gb1 = bb * 16 + lb1;
    int unit = ub * 32 + u2;
    const float* xg0p = g_xg + (size_t)gb0 * T_ * 2048 + dir * 1024 + unit;
    const float* xg1p = g_xg + (size_t)gb1 * T_ * 2048 + dir * 1024 + unit;

    unsigned h_base = (unsigned)__cvta_generic_to_shared(h_sh);
    unsigned hown_base = (unsigned)__cvta_generic_to_shared(h_own);
    unsigned a_addr = h_base + (unsigned)(lane & 15) * 528 + ((lane >> 4) << 4);

    // DSMEM gather mapping: thread -> (batch row, 16-unit segment)
    int frow = tid >> 4, fseg = tid & 15;
    int peer = fseg >> 1;
    unsigned fl = hown_base + (unsigned)frow * 64 + (fseg & 1) * 32;
    unsigned fill_r0 = mapa_u32(fl, peer);            // parity 0 buffer
    unsigned fill_r1 = mapa_u32(fl + 1024u, peer);    // parity 1 buffer
    __nv_bfloat16* hs_dst = &h_sh[frow * 264 + fseg * 16];

    float cst0 = 0.f, cst1 = 0.f;

    for (int s = 0; s < maxlen; ++s) {
        // prefetch xg (independent of h)
        float x00 = 0.f, x01 = 0.f, x02 = 0.f, x03 = 0.f;
        float x10 = 0.f, x11 = 0.f, x12 = 0.f, x13 = 0.f;
        int pos0 = dir ? (len0 - 1 - s) : s;
        int pos1 = dir ? (len1 - 1 - s) : s;
        bool v0 = s < len0, v1 = s < len1;
        if (v0) { const float* p = xg0p + (size_t)pos0 * 2048;
                  x00 = p[0]; x01 = p[256]; x02 = p[512]; x03 = p[768]; }
        if (v1) { const float* p = xg1p + (size_t)pos1 * 2048;
                  x10 = p[0]; x11 = p[256]; x12 = p[512]; x13 = p[768]; }

        // assemble full h into h_sh
        if (s == 0) {
            *(uint4*)hs_dst       = make_uint4(0, 0, 0, 0);
            *(uint4*)(hs_dst + 8) = make_uint4(0, 0, 0, 0);
        } else {
            unsigned ra = (s & 1) ? fill_r1 : fill_r0;
            unsigned long long t0 = ld_dsm64(ra);
            unsigned long long t1 = ld_dsm64(ra + 8);
            unsigned long long t2 = ld_dsm64(ra + 16);
            unsigned long long t3 = ld_dsm64(ra + 24);
            *(unsigned long long*)(hs_dst)      = t0;
            *(unsigned long long*)(hs_dst + 4)  = t1;
            *(unsigned long long*)(hs_dst + 8)  = t2;
            *(unsigned long long*)(hs_dst + 12) = t3;
        }
        __syncthreads();

        // recurrent mma: pre[16][128] = h @ Wslice^T
        float acc[2][4];
#pragma unroll
        for (int p = 0; p < 2; ++p)
#pragma unroll
            for (int r = 0; r < 4; ++r) acc[p][r] = 0.f;
#pragma unroll
        for (int kt = 0; kt < 16; ++kt) {
            unsigned A0, A1, A2, A3;
            ldsm4(A0, A1, A2, A3, a_addr + kt * 32);
            mma_bf(acc[0][0], acc[0][1], acc[0][2], acc[0][3],
                   A0, A1, A2, A3, bfr[kt][0][0], bfr[kt][0][1]);
            mma_bf(acc[1][0], acc[1][1], acc[1][2], acc[1][3],
                   A0, A1, A2, A3, bfr[kt][1][0], bfr[kt][1][1]);
        }
        {
            int r = lane >> 2;
#pragma unroll
            for (int p = 0; p < 2; ++p) {
                int c = 16 * w + 8 * p + 2 * (lane & 3);
                *(float2*)&pre_sh[r * 132 + c]       = make_float2(acc[p][0], acc[p][1]);
                *(float2*)&pre_sh[(r + 8) * 132 + c] = make_float2(acc[p][2], acc[p][3]);
            }
        }
        __syncthreads();

        int wbuf = (s + 1) & 1;
        if (v0) {
            const float* pr = pre_sh + lb0 * 132 + u2;
            float a0 = x00 + pr[0], a1 = x01 + pr[32], a2 = x02 + pr[64], a3 = x03 + pr[96];
            cst0 = sigm(a1) * cst0 + sigm(a0) * tanh_(a2);
            float hv = sigm(a3) * tanh_(cst0);
            h_own[wbuf][lb0 * 32 + u2] = __float2bfloat16(hv);
            size_t xoff = ((size_t)gb0 * T_ + pos0) * E_ + dir * H_ + unit;
            if (out_fp32) g_xA[xoff] = hv; else g_xbfB[xoff] = __float2bfloat16(hv);
        }
        if (v1) {
            const float* pr = pre_sh + lb1 * 132 + u2;
            float a0 = x10 + pr[0], a1 = x11 + pr[32], a2 = x12 + pr[64], a3 = x13 + pr[96];
            cst1 = sigm(a1) * cst1 + sigm(a0) * tanh_(a2);
            float hv = sigm(a3) * tanh_(cst1);
            h_own[wbuf][lb1 * 32 + u2] = __float2bfloat16(hv);
            size_t xoff = ((size_t)gb1 * T_ + pos1) * E_ + dir * H_ + unit;
            if (out_fp32) g_xA[xoff] = hv; else g_xbfB[xoff] = __float2bfloat16(hv);
        }

        asm volatile("barrier.cluster.arrive.aligned;" ::: "memory");
        asm volatile("barrier.cluster.wait.aligned;" ::: "memory");
    }
}

// ---------------- emissions -----------------------------------------------------
__global__ void k_emis(const float* __restrict__ fc_w, const float* __restrict__ fc_b) {
    int w = blockIdx.x * 8 + (threadIdx.x >> 5);
    int lane = threadIdx.x & 31;
    int j = lane < NT_ ? lane : 0;
    const float* x = g_xA + (size_t)w * E_;
    float acc = fc_b[j];
#pragma unroll 4
    for (int k = 0; k < E_; k += 4) {
        float4 xv = *(const float4*)(x + k);
        acc += xv.x * fc_w[(k + 0) * NT_ + j] + xv.y * fc_w[(k + 1) * NT_ + j]
             + xv.z * fc_w[(k + 2) * NT_ + j] + xv.w * fc_w[(k + 3) * NT_ + j];
    }
    if (lane < NT_) g_em[(size_t)w * NT_ + lane] = acc;
}

// ---------------- CRF -----------------------------------------------------------
__global__ void k_crf(const int* __restrict__ tags, const int* __restrict__ lengths,
                      const float* __restrict__ crf_start, const float* __restrict__ crf_end,
                      const float* __restrict__ crf_trans) {
    int b = blockIdx.x;
    int lane = threadIdx.x;
    int len = lengths[b];
    const int* tg = tags + b * T_;
    const float* em = g_em + (size_t)b * T_ * NT_;

    float part = 0.f;
    for (int t = lane; t < T_; t += 32) {
        if (t < len) {
            int tt = tg[t];
            part += em[t * NT_ + tt];
            if (t >= 1) part += crf_trans[tg[t - 1] * NT_ + tt];
        }
    }
#pragma unroll
    for (int o = 16; o; o >>= 1) part += __shfl_xor_sync(0xFFFFFFFFu, part, o);
    float numer = part + crf_start[tg[0]] + crf_end[tg[len - 1]];

    int j = lane < NT_ ? lane : 0;
    float etr[NT_];
#pragma unroll
    for (int i = 0; i < NT_; i++) etr[i] = expf(crf_trans[i * NT_ + j]);

    float s = crf_start[j] + em[j];
    for (int t = 1; t < len; ++t) {
        float sl = (lane < NT_) ? s : -1e30f;
        float m = sl;
#pragma unroll
        for (int o = 16; o; o >>= 1) m = fmaxf(m, __shfl_xor_sync(0xFFFFFFFFu, m, o));
        float es = expf(s - m);          // exp(s_j - m), valid for lane<NT
        float z = 0.f;
#pragma unroll
        for (int i = 0; i < NT_; i++) {
            float ei = __shfl_sync(0xFFFFFFFFu, es, i);
            z += ei * etr[i];
        }
        s = m + logf(z) + em[t * NT_ + j];
    }
    s += crf_end[j];
    float sj = (lane < NT_) ? s : -1e30f;
    float mm = sj;
#pragma unroll
    for (int o = 16; o; o >>= 1) mm = fmaxf(mm, __shfl_xor_sync(0xFFFFFFFFu, mm, o));
    float zz = (lane < NT_) ? expf(sj - mm) : 0.f;
#pragma unroll
    for (int o = 16; o; o >>= 1) zz += __shfl_xor_sync(0xFFFFFFFFu, zz, o);
    float logZ = mm + logf(zz);
    if (lane == 0) g_llh[b] = numer - logZ;
}

// ---------------- final reduction ----------------------------------------------
__global__ void k_reduce(float* __restrict__ out) {
    int lane = threadIdx.x;
    float v = g_llh[lane];
    __shared__ float tmp[2];
#pragma unroll
    for (int o = 16; o; o >>= 1) v += __shfl_xor_sync(0xFFFFFFFFu, v, o);
    if ((lane & 31) == 0) tmp[lane >> 5] = v;
    __syncthreads();
    if (lane == 0) out[0] = -(tmp[0] + tmp[1]);
}

// ---------------- host launcher -------------------------------------------------
extern "C" void kernel_launch(void* const* d_in, const int* in_sizes, int n_in,
                              void* d_out, int out_size) {
    const int*   ids   = (const int*)d_in[0];
    const int*   lens  = (const int*)d_in[1];
    const int*   tags  = (const int*)d_in[2];
    const float* embed = (const float*)d_in[3];
    const float* w_ih  = (const float*)d_in[4];
    const float* w_hh  = (const float*)d_in[5];
    const float* b_ih  = (const float*)d_in[6];
    const float* b_hh  = (const float*)d_in[7];
    const float* fc_w  = (const float*)d_in[8];
    const float* fc_b  = (const float*)d_in[9];
    const float* c_st  = (const float*)d_in[10];
    const float* c_en  = (const float*)d_in[11];
    const float* c_tr  = (const float*)d_in[12];
    float* out = (float*)d_out;

    k_wcvt<<<2048, 256>>>(w_ih);
    k_gather<<<B_ * T_, 128>>>(ids, embed);

    // layer 0
    k_gemm_bf<<<dim3(16, 256), 256>>>(b_ih, b_hh, 0);
    k_zerobf<<<8192, 256>>>();
    k_lstm<<<64, 256>>>(w_hh, lens, 0, 0);

    // layer 1
    k_gemm_bf<<<dim3(16, 256), 256>>>(b_ih, b_hh, 1);
    k_zerof<<<16384, 256>>>();
    k_lstm<<<64, 256>>>(w_hh, lens, 1, 1);

    k_emis<<<B_ * T_ / 8, 256>>>(fc_w, fc_b);
    k_crf<<<B_, 32>>>(tags, lens, c_st, c_en, c_tr);
    k_reduce<<<1, 64>>>(out);
}